// round 2
// baseline (speedup 1.0000x reference)
#include <cuda_runtime.h>
#include <math.h>

#define LSEQ 512
#define CP   128
#define FEAT 64

// ---- precomputed tables (device globals; no allocation) ----
__device__ float g_pi[LSEQ * FEAT];     // node projection
__device__ float g_A [LSEQ * CP];       // b1 + p_i[i] . W1[:,0:64]
__device__ float g_B [LSEQ * CP];       // p_i[j] . W1[:,64:128]
__device__ float g_C [1023 * CP];       // relpos path . W1[:,128:192], indexed by (i-j+511)

// =====================  precompute kernels  =====================

__global__ void k_node(const float* __restrict__ s, const float* __restrict__ Wsp,
                       const float* __restrict__ bsp) {
    __shared__ float srow[256];
    const int i = blockIdx.x, f = threadIdx.x;   // 64 threads
    for (int d = f; d < 256; d += 64) srow[d] = s[i * 256 + d];
    __syncthreads();
    float acc = bsp[f];
    const float* w = Wsp + f * 256;
    #pragma unroll 8
    for (int d = 0; d < 256; d++) acc = fmaf(srow[d], w[d], acc);
    g_pi[i * FEAT + f] = acc;
}

__global__ void k_AB(const float* __restrict__ W1, const float* __restrict__ b1) {
    __shared__ float prow[FEAT];
    const int i = blockIdx.x, p = threadIdx.x;   // 128 threads
    if (p < FEAT) prow[p] = g_pi[i * FEAT + p];
    __syncthreads();
    float a = b1[p], b = 0.0f;
    const float* w = W1 + p * 256;
    #pragma unroll
    for (int f = 0; f < FEAT; f++) {
        a = fmaf(prow[f], w[f], a);
        b = fmaf(prow[f], w[64 + f], b);
    }
    g_A[i * CP + p] = a;
    g_B[i * CP + p] = b;
}

__global__ void k_C(const float* __restrict__ Wrp, const float* __restrict__ brp,
                    const float* __restrict__ W1) {
    __shared__ float emb[64];
    __shared__ float rp[64];
    const int d = blockIdx.x;          // 0..1022  -> rel = d - 511
    const int tid = threadIdx.x;       // 128 threads
    if (tid < 32) {
        double rel = (double)(d - 511);
        double denom = pow(2056.0, (double)(2 * tid) / 64.0);
        double ang = rel * 3.14159265358979323846 / denom;
        emb[tid]      = (float)sin(ang);
        emb[32 + tid] = (float)cos(ang);
    }
    __syncthreads();
    if (tid < 64) {
        float acc = brp[tid];
        const float* w = Wrp + tid * 64;
        #pragma unroll
        for (int g = 0; g < 64; g++) acc = fmaf(emb[g], w[g], acc);
        rp[tid] = acc;
    }
    __syncthreads();
    float acc = 0.0f;
    const float* w = W1 + tid * 256 + 128;
    #pragma unroll
    for (int g = 0; g < 64; g++) acc = fmaf(rp[g], w[g], acc);
    g_C[d * CP + tid] = acc;
}

// =====================  fused main kernel  =====================
// Tile: 16 i-rows x 8 j-cols = 128 pairs (M), 128 output channels (N).
// smem layout (floats):
//   sW2 : [128][132]  (W2 transposed, padded)          16896
//   sE  : [128][65]   (per-pair small edge, K=64)       8320   } overlapped
//   sW1 : [64][132]   (W1[:,192:256] transposed, pad)   8448   } with sH
//   sH  : [128][129]  (relu hidden, padded)            16512   }
#define SW2S 132
#define SW1S 132
#define ES   65
#define HS   129
#define SMEM_FLOATS (128 * SW2S + (128 * ES + 64 * SW1S))

__global__ __launch_bounds__(256, 1)
void k_main(const float* __restrict__ t, const float* __restrict__ sct,
            const float* __restrict__ pre, const float* __restrict__ W1,
            const float* __restrict__ W2, const float* __restrict__ b2v,
            float* __restrict__ out) {
    extern __shared__ float smem[];
    float* sW2 = smem;                    // 128*132
    float* sE  = smem + 128 * SW2S;       // 128*65
    float* sW1 = sE + 128 * ES;           // 64*132
    float* sH  = smem + 128 * SW2S;       // overlaps sE+sW1 (used after sync)

    const int tid = threadIdx.x;
    const int i0 = blockIdx.y * 16, j0 = blockIdx.x * 8;

    // stage W1 slice transposed: sW1[k][p] = W1[p][192+k]
    for (int idx = tid; idx < 64 * 128; idx += 256) {
        int p = idx >> 6, k = idx & 63;                  // k fast -> coalesced global read
        sW1[k * SW1S + p] = W1[p * 256 + 192 + k];
    }
    // stage W2 transposed: sW2[p][q] = W2[q][p]
    for (int idx = tid; idx < 128 * 128; idx += 256) {
        int q = idx >> 7, p = idx & 127;                 // p fast -> coalesced global read
        sW2[p * SW2S + q] = W2[q * 128 + p];
    }
    // build per-pair small edge features E[m][0:64] = [rbf_t(22), rbf_sc(22), pre(20)]
    {
        const int m = tid & 127, half = tid >> 7;        // 2 threads per pair
        const int i = i0 + (m >> 3), j = j0 + (m & 7);
        const float* P = half ? sct : t;
        float dx = P[i * 3 + 0] - P[j * 3 + 0];
        float dy = P[i * 3 + 1] - P[j * 3 + 1];
        float dz = P[i * 3 + 2] - P[j * 3 + 2];
        float dist = sqrtf(dx * dx + dy * dy + dz * dz);
        const float inv_sig = 22.0f / 20.0f;             // 1/sigma, sigma = 20/22
        float* e = sE + m * ES + half * 22;
        #pragma unroll
        for (int bb = 0; bb < 22; bb++) {
            float r = (dist - bb * (20.0f / 21.0f)) * inv_sig;
            e[bb] = __expf(-r * r);
        }
        const float* pp = pre + ((size_t)i * LSEQ + j) * 20 + half * 10;
        float* e2 = sE + m * ES + 44 + half * 10;
        #pragma unroll
        for (int c = 0; c < 10; c++) e2[c] = pp[c];
    }
    __syncthreads();

    const int ty = tid >> 4, tx = tid & 15;
    const int m0 = ty * 8, n0 = tx * 8;

    // ---- GEMM1: acc[m][n] = sum_k E[m][k] * W1s[k][n]  (K=64) ----
    float acc[8][8] = {};
    #pragma unroll 4
    for (int k = 0; k < 64; k++) {
        float a[8];
        #pragma unroll
        for (int mi = 0; mi < 8; mi++) a[mi] = sE[(m0 + mi) * ES + k];
        float4 w0 = *(const float4*)&sW1[k * SW1S + n0];
        float4 w1 = *(const float4*)&sW1[k * SW1S + n0 + 4];
        float w[8] = {w0.x, w0.y, w0.z, w0.w, w1.x, w1.y, w1.z, w1.w};
        #pragma unroll
        for (int mi = 0; mi < 8; mi++)
            #pragma unroll
            for (int ni = 0; ni < 8; ni++)
                acc[mi][ni] = fmaf(a[mi], w[ni], acc[mi][ni]);
    }
    __syncthreads();   // done reading sE/sW1; safe to overwrite with sH

    // epilogue1: + A[i] + B[j] + C[i-j] (b1 folded into A), relu, store H
    #pragma unroll
    for (int mi = 0; mi < 8; mi++) {
        const int m = m0 + mi;
        const int i = i0 + (m >> 3), j = j0 + (m & 7);
        const float4* Ar = (const float4*)(g_A + i * CP + n0);
        const float4* Br = (const float4*)(g_B + j * CP + n0);
        const float4* Cr = (const float4*)(g_C + (i - j + 511) * CP + n0);
        float4 a0 = Ar[0], a1 = Ar[1];
        float4 bb0 = Br[0], bb1 = Br[1];
        float4 c0 = Cr[0], c1 = Cr[1];
        float add[8] = {a0.x + bb0.x + c0.x, a0.y + bb0.y + c0.y,
                        a0.z + bb0.z + c0.z, a0.w + bb0.w + c0.w,
                        a1.x + bb1.x + c1.x, a1.y + bb1.y + c1.y,
                        a1.z + bb1.z + c1.z, a1.w + bb1.w + c1.w};
        #pragma unroll
        for (int ni = 0; ni < 8; ni++)
            sH[m * HS + n0 + ni] = fmaxf(acc[mi][ni] + add[ni], 0.0f);
    }
    __syncthreads();

    // ---- GEMM2: acc2[m][q] = sum_p H[m][p] * W2T[p][q]  (K=128) ----
    float acc2[8][8] = {};
    #pragma unroll 2
    for (int k = 0; k < 128; k++) {
        float h[8];
        #pragma unroll
        for (int mi = 0; mi < 8; mi++) h[mi] = sH[(m0 + mi) * HS + k];
        float4 w0 = *(const float4*)&sW2[k * SW2S + n0];
        float4 w1 = *(const float4*)&sW2[k * SW2S + n0 + 4];
        float w[8] = {w0.x, w0.y, w0.z, w0.w, w1.x, w1.y, w1.z, w1.w};
        #pragma unroll
        for (int mi = 0; mi < 8; mi++)
            #pragma unroll
            for (int ni = 0; ni < 8; ni++)
                acc2[mi][ni] = fmaf(h[mi], w[ni], acc2[mi][ni]);
    }

    // epilogue2: + b2, write out (float4, coalesced)
    float4 bv0 = *(const float4*)&b2v[n0];
    float4 bv1 = *(const float4*)&b2v[n0 + 4];
    #pragma unroll
    for (int mi = 0; mi < 8; mi++) {
        const int m = m0 + mi;
        const int i = i0 + (m >> 3), j = j0 + (m & 7);
        float* o = out + ((size_t)i * LSEQ + j) * CP + n0;
        float4 r0, r1;
        r0.x = acc2[mi][0] + bv0.x; r0.y = acc2[mi][1] + bv0.y;
        r0.z = acc2[mi][2] + bv0.z; r0.w = acc2[mi][3] + bv0.w;
        r1.x = acc2[mi][4] + bv1.x; r1.y = acc2[mi][5] + bv1.y;
        r1.z = acc2[mi][6] + bv1.z; r1.w = acc2[mi][7] + bv1.w;
        *(float4*)o = r0;
        *(float4*)(o + 4) = r1;
    }
}

// =====================  launch  =====================

extern "C" void kernel_launch(void* const* d_in, const int* in_sizes, int n_in,
                              void* d_out, int out_size) {
    const float* s   = (const float*)d_in[0];
    const float* t   = (const float*)d_in[1];
    const float* sct = (const float*)d_in[2];
    const float* pre = (const float*)d_in[3];
    // d_in[4] = p_mask (unused by reference)
    const float* Wsp = (const float*)d_in[5];
    const float* bsp = (const float*)d_in[6];
    const float* Wrp = (const float*)d_in[7];
    const float* brp = (const float*)d_in[8];
    const float* W1  = (const float*)d_in[9];
    const float* b1  = (const float*)d_in[10];
    const float* W2  = (const float*)d_in[11];
    const float* b2  = (const float*)d_in[12];
    float* out = (float*)d_out;

    k_node<<<LSEQ, 64>>>(s, Wsp, bsp);
    k_AB<<<LSEQ, 128>>>(W1, b1);
    k_C<<<1023, 128>>>(Wrp, brp, W1);

    size_t smem_bytes = (size_t)SMEM_FLOATS * sizeof(float);
    cudaFuncSetAttribute(k_main, cudaFuncAttributeMaxDynamicSharedMemorySize,
                         (int)smem_bytes);
    dim3 grid(LSEQ / 8, LSEQ / 16);   // (64, 32)
    k_main<<<grid, 256, smem_bytes>>>(t, sct, pre, W1, W2, b2, out);
}

// round 5
// speedup vs baseline: 1.2586x; 1.2586x over previous
#include <cuda_runtime.h>
#include <cuda_bf16.h>
#include <mma.h>
#include <cstdint>
#include <math.h>

using namespace nvcuda;

#define LSEQ 512
#define CP   128

// ======================= device globals (no allocation) =======================
__device__ float g_A[LSEQ * CP];            // b1 + p_i[i] . W1[:,0:64]
__device__ float g_B[LSEQ * CP];            // p_i[j] . W1[:,64:128]
__device__ float g_C[1023 * CP];            // relpos path . W1[:,128:192]
__device__ unsigned short g_W1h[64 * 128];  // W1[:,192:256]^T  bf16 hi  [k][n]
__device__ unsigned short g_W1l[64 * 128];  //                  bf16 lo
__device__ unsigned short g_W2h[128 * 128]; // W2^T bf16 hi  [p][q]
__device__ unsigned short g_W2l[128 * 128]; //      bf16 lo

__device__ __forceinline__ void split2(float v, unsigned short& h, unsigned short& l) {
    __nv_bfloat16 hb = __float2bfloat16_rn(v);
    float r = v - __bfloat162float(hb);
    h = __bfloat16_as_ushort(hb);
    l = __bfloat16_as_ushort(__float2bfloat16_rn(r));
}

// ======================= prep kernel 1: node proj + A/B tables =======================
__global__ void k_prep1(const float* __restrict__ s, const float* __restrict__ Wsp,
                        const float* __restrict__ bsp, const float* __restrict__ W1,
                        const float* __restrict__ b1) {
    __shared__ float srow[256];
    __shared__ float prow[64];
    const int i = blockIdx.x, tid = threadIdx.x;  // 128 threads
    for (int d = tid; d < 256; d += 128) srow[d] = s[i * 256 + d];
    __syncthreads();
    if (tid < 64) {
        float acc = bsp[tid];
        const float* w = Wsp + tid * 256;
        #pragma unroll 8
        for (int d = 0; d < 256; d++) acc = fmaf(srow[d], w[d], acc);
        prow[tid] = acc;
    }
    __syncthreads();
    float a = b1[tid], b = 0.0f;
    const float* w = W1 + tid * 256;
    #pragma unroll
    for (int f = 0; f < 64; f++) {
        a = fmaf(prow[f], w[f], a);
        b = fmaf(prow[f], w[64 + f], b);
    }
    g_A[i * CP + tid] = a;
    g_B[i * CP + tid] = b;
}

// ======================= prep kernel 2: C table + bf16 weight splits =======================
__global__ void k_prep2(const float* __restrict__ Wrp, const float* __restrict__ brp,
                        const float* __restrict__ W1, const float* __restrict__ W2) {
    const int tid = threadIdx.x;  // 128 threads
    const int blk = blockIdx.x;
    if (blk < 1023) {
        __shared__ float emb[64];
        __shared__ float rp[64];
        const int d = blk;  // rel = d - 511
        if (tid < 32) {
            // x = rel / 2056^(k/32);  angle = pi*x  -> sincospif (exact reduction)
            const float L2 = 11.005624549193878f;   // log2(2056)
            float x = (float)(d - 511) * exp2f(-(float)tid * (L2 / 32.0f));
            float sv, cv;
            sincospif(x, &sv, &cv);
            emb[tid] = sv;
            emb[32 + tid] = cv;
        }
        __syncthreads();
        if (tid < 64) {
            float acc = brp[tid];
            const float* w = Wrp + tid * 64;
            #pragma unroll
            for (int g = 0; g < 64; g++) acc = fmaf(emb[g], w[g], acc);
            rp[tid] = acc;
        }
        __syncthreads();
        float acc = 0.0f;
        const float* w = W1 + tid * 256 + 128;
        #pragma unroll
        for (int g = 0; g < 64; g++) acc = fmaf(rp[g], w[g], acc);
        g_C[d * CP + tid] = acc;
    } else if (blk == 1023) {
        for (int x = tid; x < 64 * 128; x += 128) {
            int k = x >> 7, n = x & 127;
            unsigned short h, l;
            split2(W1[n * 256 + 192 + k], h, l);
            g_W1h[x] = h;
            g_W1l[x] = l;
        }
    } else {
        for (int x = tid; x < 128 * 128; x += 128) {
            int p = x >> 7, q = x & 127;
            unsigned short h, l;
            split2(W2[q * 128 + p], h, l);
            g_W2h[x] = h;
            g_W2l[x] = l;
        }
    }
}

// ======================= main persistent wmma kernel =======================
// tile = 1 i-row x 128 j (M=128 pairs) x 128 channels (N). 2048 tiles.
// smem (bytes):
#define E_LD  72
#define W_LD  136
#define ST_LD 68
#define OFF_E    0                       // E hi  128x72 bf16 = 18432 (reused: fp32 stage 128x68 = 34816)
#define OFF_EL   18432                   // E lo
#define OFF_W1   36864                   // W1 hi 64x136 bf16 = 17408
#define OFF_W1L  54272                   // W1 lo
#define OFF_W2   71680                   // W2 hi 128x136 bf16 = 34816
#define OFF_W2L  106496                  // W2 lo
#define OFF_H    141312                  // H hi 128x136 bf16 = 34816
#define OFF_HL   176128                  // H lo
#define SMEM_TOTAL 210944

__global__ __launch_bounds__(256, 1)
void k_main(const float* __restrict__ t, const float* __restrict__ sct,
            const float* __restrict__ pre, const float* __restrict__ b2v,
            float* __restrict__ out) {
    extern __shared__ char smem[];
    __nv_bfloat16* sEh  = (__nv_bfloat16*)(smem + OFF_E);
    __nv_bfloat16* sEl  = (__nv_bfloat16*)(smem + OFF_EL);
    __nv_bfloat16* sW1h = (__nv_bfloat16*)(smem + OFF_W1);
    __nv_bfloat16* sW1l = (__nv_bfloat16*)(smem + OFF_W1L);
    __nv_bfloat16* sW2h = (__nv_bfloat16*)(smem + OFF_W2);
    __nv_bfloat16* sW2l = (__nv_bfloat16*)(smem + OFF_W2L);
    __nv_bfloat16* sHh  = (__nv_bfloat16*)(smem + OFF_H);
    __nv_bfloat16* sHl  = (__nv_bfloat16*)(smem + OFF_HL);
    float* stage = (float*)(smem + OFF_E);   // overlays E after GEMM1 / GEMM2

    const int tid = threadIdx.x;
    const int wid = tid >> 5;
    const int wm = wid >> 1;      // 0..3 -> M rows [wm*32, +32)
    const int wn = wid & 1;       // 0..1 -> N cols [wn*64, +64)

    // ---- stage pre-split weights once (persistent CTA) ----
    {
        uint32_t* d1h = (uint32_t*)(smem + OFF_W1);
        uint32_t* d1l = (uint32_t*)(smem + OFF_W1L);
        const uint32_t* s1h = (const uint32_t*)g_W1h;
        const uint32_t* s1l = (const uint32_t*)g_W1l;
        for (int x = tid; x < 64 * 64; x += 256) {
            int k = x >> 6, c = x & 63;
            d1h[k * 68 + c] = s1h[x];
            d1l[k * 68 + c] = s1l[x];
        }
        uint32_t* d2h = (uint32_t*)(smem + OFF_W2);
        uint32_t* d2l = (uint32_t*)(smem + OFF_W2L);
        const uint32_t* s2h = (const uint32_t*)g_W2h;
        const uint32_t* s2l = (const uint32_t*)g_W2l;
        for (int x = tid; x < 128 * 64; x += 256) {
            int p = x >> 6, c = x & 63;
            d2h[p * 68 + c] = s2h[x];
            d2l[p * 68 + c] = s2l[x];
        }
        __syncthreads();
    }

    const __nv_bfloat16* EA[3]  = {sEh, sEl, sEh};
    const __nv_bfloat16* W1B[3] = {sW1h, sW1h, sW1l};
    const __nv_bfloat16* HA[3]  = {sHh, sHl, sHh};
    const __nv_bfloat16* W2B[3] = {sW2h, sW2h, sW2l};

    for (int tile = blockIdx.x; tile < 2048; tile += gridDim.x) {
        const int i = tile >> 2;
        const int j0 = (tile & 3) << 7;

        // ---- build E: [rbf_t(22), rbf_sc(22), pre(20)] -> bf16 hi/lo ----
        if (tid < 128) {
            const int m = tid, j = j0 + m;
            float dx = t[3 * i + 0] - t[3 * j + 0];
            float dy = t[3 * i + 1] - t[3 * j + 1];
            float dz = t[3 * i + 2] - t[3 * j + 2];
            float dT = sqrtf(dx * dx + dy * dy + dz * dz);
            dx = sct[3 * i + 0] - sct[3 * j + 0];
            dy = sct[3 * i + 1] - sct[3 * j + 1];
            dz = sct[3 * i + 2] - sct[3 * j + 2];
            float dS = sqrtf(dx * dx + dy * dy + dz * dz);
            const float inv_sig = 22.0f / 20.0f, step = 20.0f / 21.0f;
            float e[44];
            #pragma unroll
            for (int k = 0; k < 22; k++) {
                float r1 = (dT - k * step) * inv_sig;
                e[k] = __expf(-r1 * r1);
                float r2 = (dS - k * step) * inv_sig;
                e[22 + k] = __expf(-r2 * r2);
            }
            uint32_t* Eh = (uint32_t*)(sEh + m * E_LD);
            uint32_t* El = (uint32_t*)(sEl + m * E_LD);
            #pragma unroll
            for (int c = 0; c < 22; c++) {
                unsigned short h0, l0, h1, l1;
                split2(e[2 * c], h0, l0);
                split2(e[2 * c + 1], h1, l1);
                Eh[c] = (uint32_t)h0 | ((uint32_t)h1 << 16);
                El[c] = (uint32_t)l0 | ((uint32_t)l1 << 16);
            }
        } else {
            const int m = tid - 128, j = j0 + m;
            const float4* pp = (const float4*)(pre + ((size_t)(i * LSEQ + j)) * 20);
            float e[20];
            #pragma unroll
            for (int c = 0; c < 5; c++) {
                float4 v = pp[c];
                e[4 * c + 0] = v.x; e[4 * c + 1] = v.y;
                e[4 * c + 2] = v.z; e[4 * c + 3] = v.w;
            }
            uint32_t* Eh = (uint32_t*)(sEh + m * E_LD + 44);
            uint32_t* El = (uint32_t*)(sEl + m * E_LD + 44);
            #pragma unroll
            for (int c = 0; c < 10; c++) {
                unsigned short h0, l0, h1, l1;
                split2(e[2 * c], h0, l0);
                split2(e[2 * c + 1], h1, l1);
                Eh[c] = (uint32_t)h0 | ((uint32_t)h1 << 16);
                El[c] = (uint32_t)l0 | ((uint32_t)l1 << 16);
            }
        }
        __syncthreads();

        wmma::fragment<wmma::accumulator, 16, 16, 16, float> acc[2][4];

        // ---- GEMM1: D1 = E @ W1s  (K=64, 3 split passes) ----
        #pragma unroll
        for (int mi = 0; mi < 2; mi++)
            #pragma unroll
            for (int nb = 0; nb < 4; nb++) wmma::fill_fragment(acc[mi][nb], 0.0f);
        #pragma unroll
        for (int pass = 0; pass < 3; pass++) {
            const __nv_bfloat16* Ab = EA[pass];
            const __nv_bfloat16* Bb = W1B[pass];
            #pragma unroll
            for (int ks = 0; ks < 4; ks++) {
                wmma::fragment<wmma::matrix_a, 16, 16, 16, __nv_bfloat16, wmma::row_major> a0, a1;
                wmma::load_matrix_sync(a0, Ab + (wm * 32) * E_LD + ks * 16, E_LD);
                wmma::load_matrix_sync(a1, Ab + (wm * 32 + 16) * E_LD + ks * 16, E_LD);
                #pragma unroll
                for (int nb = 0; nb < 4; nb++) {
                    wmma::fragment<wmma::matrix_b, 16, 16, 16, __nv_bfloat16, wmma::row_major> bf;
                    wmma::load_matrix_sync(bf, Bb + (ks * 16) * W_LD + wn * 64 + nb * 16, W_LD);
                    wmma::mma_sync(acc[0][nb], a0, bf, acc[0][nb]);
                    wmma::mma_sync(acc[1][nb], a1, bf, acc[1][nb]);
                }
            }
        }
        __syncthreads();   // all E reads done; stage may overwrite E region

        // ---- epilogue1: H = relu(D1 + A[i] + B[j] + C[i-j]) -> bf16 hi/lo ----
        #pragma unroll
        for (int r = 0; r < 2; r++) {
            if (wn == r) {
                #pragma unroll
                for (int mi = 0; mi < 2; mi++)
                    #pragma unroll
                    for (int nb = 0; nb < 4; nb++)
                        wmma::store_matrix_sync(stage + (wm * 32 + mi * 16) * ST_LD + nb * 16,
                                                acc[mi][nb], ST_LD, wmma::mem_row_major);
            }
            __syncthreads();
            const int m = tid >> 1, half = tid & 1;
            const int cb = r * 64 + half * 32;
            const int j = j0 + m;
            const float4* S4 = (const float4*)(stage + m * ST_LD + half * 32);
            const float4* A4 = (const float4*)(g_A + i * CP + cb);
            const float4* B4 = (const float4*)(g_B + j * CP + cb);
            const float4* C4 = (const float4*)(g_C + (i - j + 511) * CP + cb);
            uint32_t* Hh = (uint32_t*)(sHh + m * W_LD + cb);
            uint32_t* Hl = (uint32_t*)(sHl + m * W_LD + cb);
            #pragma unroll
            for (int u = 0; u < 8; u++) {
                float4 sv = S4[u], av = A4[u], bv = B4[u], cv = C4[u];
                float v0 = fmaxf(sv.x + av.x + bv.x + cv.x, 0.0f);
                float v1 = fmaxf(sv.y + av.y + bv.y + cv.y, 0.0f);
                float v2 = fmaxf(sv.z + av.z + bv.z + cv.z, 0.0f);
                float v3 = fmaxf(sv.w + av.w + bv.w + cv.w, 0.0f);
                unsigned short h0, l0, h1, l1, h2, l2, h3, l3;
                split2(v0, h0, l0); split2(v1, h1, l1);
                split2(v2, h2, l2); split2(v3, h3, l3);
                Hh[2 * u]     = (uint32_t)h0 | ((uint32_t)h1 << 16);
                Hh[2 * u + 1] = (uint32_t)h2 | ((uint32_t)h3 << 16);
                Hl[2 * u]     = (uint32_t)l0 | ((uint32_t)l1 << 16);
                Hl[2 * u + 1] = (uint32_t)l2 | ((uint32_t)l3 << 16);
            }
            __syncthreads();
        }

        // ---- GEMM2: D2 = H @ W2t  (K=128, 3 split passes) ----
        #pragma unroll
        for (int mi = 0; mi < 2; mi++)
            #pragma unroll
            for (int nb = 0; nb < 4; nb++) wmma::fill_fragment(acc[mi][nb], 0.0f);
        #pragma unroll
        for (int pass = 0; pass < 3; pass++) {
            const __nv_bfloat16* Ab = HA[pass];
            const __nv_bfloat16* Bb = W2B[pass];
            #pragma unroll
            for (int ks = 0; ks < 8; ks++) {
                wmma::fragment<wmma::matrix_a, 16, 16, 16, __nv_bfloat16, wmma::row_major> a0, a1;
                wmma::load_matrix_sync(a0, Ab + (wm * 32) * W_LD + ks * 16, W_LD);
                wmma::load_matrix_sync(a1, Ab + (wm * 32 + 16) * W_LD + ks * 16, W_LD);
                #pragma unroll
                for (int nb = 0; nb < 4; nb++) {
                    wmma::fragment<wmma::matrix_b, 16, 16, 16, __nv_bfloat16, wmma::row_major> bf;
                    wmma::load_matrix_sync(bf, Bb + (ks * 16) * W_LD + wn * 64 + nb * 16, W_LD);
                    wmma::mma_sync(acc[0][nb], a0, bf, acc[0][nb]);
                    wmma::mma_sync(acc[1][nb], a1, bf, acc[1][nb]);
                }
            }
        }

        // ---- epilogue2: out = D2 + b2 (contiguous 128x128 block) ----
        #pragma unroll
        for (int r = 0; r < 2; r++) {
            if (wn == r) {
                #pragma unroll
                for (int mi = 0; mi < 2; mi++)
                    #pragma unroll
                    for (int nb = 0; nb < 4; nb++)
                        wmma::store_matrix_sync(stage + (wm * 32 + mi * 16) * ST_LD + nb * 16,
                                                acc[mi][nb], ST_LD, wmma::mem_row_major);
            }
            __syncthreads();
            const int m = tid >> 1, half = tid & 1;
            const int cb = r * 64 + half * 32;
            const float4* S4 = (const float4*)(stage + m * ST_LD + half * 32);
            const float4* Bb = (const float4*)(b2v + cb);
            float4* O4 = (float4*)(out + ((size_t)(i * LSEQ + j0 + m)) * CP + cb);
            #pragma unroll
            for (int u = 0; u < 8; u++) {
                float4 sv = S4[u], bb = Bb[u];
                float4 rr;
                rr.x = sv.x + bb.x; rr.y = sv.y + bb.y;
                rr.z = sv.z + bb.z; rr.w = sv.w + bb.w;
                O4[u] = rr;
            }
            __syncthreads();
        }
    }
}

// ======================= launch =======================
extern "C" void kernel_launch(void* const* d_in, const int* in_sizes, int n_in,
                              void* d_out, int out_size) {
    const float* s   = (const float*)d_in[0];
    const float* t   = (const float*)d_in[1];
    const float* sct = (const float*)d_in[2];
    const float* pre = (const float*)d_in[3];
    // d_in[4] = p_mask (all-ones, unused)
    const float* Wsp = (const float*)d_in[5];
    const float* bsp = (const float*)d_in[6];
    const float* Wrp = (const float*)d_in[7];
    const float* brp = (const float*)d_in[8];
    const float* W1  = (const float*)d_in[9];
    const float* b1  = (const float*)d_in[10];
    const float* W2  = (const float*)d_in[11];
    const float* b2  = (const float*)d_in[12];
    float* out = (float*)d_out;

    k_prep1<<<LSEQ, 128>>>(s, Wsp, bsp, W1, b1);
    k_prep2<<<1025, 128>>>(Wrp, brp, W1, W2);

    cudaFuncSetAttribute(k_main, cudaFuncAttributeMaxDynamicSharedMemorySize, SMEM_TOTAL);
    k_main<<<152, 256, SMEM_TOTAL>>>(t, sct, pre, b2, out);
}

// round 7
// speedup vs baseline: 1.8292x; 1.4534x over previous
#include <cuda_runtime.h>
#include <cuda_bf16.h>
#include <mma.h>
#include <cstdint>
#include <math.h>

using namespace nvcuda;

#define LSEQ 512
#define CP   128

// ======================= device globals (no allocation) =======================
__device__ float g_A[LSEQ * CP];            // b1 + p_i[i] . W1[:,0:64]
__device__ float g_B[LSEQ * CP];            // p_i[j] . W1[:,64:128]
__device__ float g_C[1023 * CP];            // relpos path . W1[:,128:192]
__device__ unsigned short g_W1h[64 * 128];  // W1[:,192:256]^T  bf16 hi  [k][n]
__device__ unsigned short g_W1l[64 * 128];  //                  bf16 lo
__device__ unsigned short g_W2h[128 * 128]; // W2^T bf16 hi  [p][q]
__device__ unsigned short g_W2l[128 * 128]; //      bf16 lo

__device__ __forceinline__ void split2(float v, unsigned short& h, unsigned short& l) {
    __nv_bfloat16 hb = __float2bfloat16_rn(v);
    float r = v - __bfloat162float(hb);
    h = __bfloat16_as_ushort(hb);
    l = __bfloat16_as_ushort(__float2bfloat16_rn(r));
}

// ======================= prep kernel 1: node proj + A/B tables =======================
// 64 blocks x 256 threads; each block: 8 i-rows; weights staged transposed in smem.
__global__ void k_prep1(const float* __restrict__ s, const float* __restrict__ Wsp,
                        const float* __restrict__ bsp, const float* __restrict__ W1,
                        const float* __restrict__ b1) {
    extern __shared__ float sm1[];
    float* sWspT = sm1;                        // [d=256][f=64] pad 65
    float* sW1T  = sm1 + 256 * 65;             // [c=128][p=128] pad 129
    float* srow  = sW1T + 128 * 129;           // [8][256]
    float* prow  = srow + 8 * 256;             // [8][64]
    const int tid = threadIdx.x;
    const int ii0 = blockIdx.x * 8;

    for (int x = tid; x < 64 * 256; x += 256) {
        int f = x >> 8, d = x & 255;
        sWspT[d * 65 + f] = Wsp[x];
    }
    for (int x = tid; x < 128 * 128; x += 256) {
        int p = x >> 7, c = x & 127;
        sW1T[c * 129 + p] = W1[p * 256 + c];
    }
    for (int x = tid; x < 8 * 256; x += 256)
        srow[x] = s[ii0 * 256 + x];
    __syncthreads();

    {
        const int f = tid & 63, il = tid >> 6;
        #pragma unroll
        for (int rep = 0; rep < 2; rep++) {
            const int i_loc = rep * 4 + il;
            float acc = bsp[f];
            const float* sr = srow + i_loc * 256;
            #pragma unroll 8
            for (int d = 0; d < 256; d++) acc = fmaf(sr[d], sWspT[d * 65 + f], acc);
            prow[i_loc * 64 + f] = acc;
        }
    }
    __syncthreads();
    {
        const int p = tid & 127, il = tid >> 7;
        #pragma unroll
        for (int rep = 0; rep < 4; rep++) {
            const int i_loc = rep * 2 + il;
            float a = b1[p], b = 0.0f;
            const float* pr = prow + i_loc * 64;
            #pragma unroll
            for (int fx = 0; fx < 64; fx++) {
                float pv = pr[fx];
                a = fmaf(pv, sW1T[fx * 129 + p], a);
                b = fmaf(pv, sW1T[(64 + fx) * 129 + p], b);
            }
            g_A[(ii0 + i_loc) * CP + p] = a;
            g_B[(ii0 + i_loc) * CP + p] = b;
        }
    }
}

// ======================= prep kernel 2: C table + bf16 weight splits =======================
// blocks 0..15: C table (64 d's each, weights staged transposed); 16: W1 split; 17: W2 split.
__global__ void k_prep2(const float* __restrict__ Wrp, const float* __restrict__ brp,
                        const float* __restrict__ W1, const float* __restrict__ W2) {
    extern __shared__ float sm2[];
    const int tid = threadIdx.x;   // 256
    const int blk = blockIdx.x;
    if (blk < 16) {
        float* sWrpT  = sm2;                   // [g=64][f=64] pad 65
        float* sW1cT  = sm2 + 64 * 65;         // [g=64][p=128] pad 129
        float* semb   = sW1cT + 64 * 129;      // [4][64]
        float* srp    = semb + 4 * 64;         // [4][64]
        for (int x = tid; x < 64 * 64; x += 256) {
            int f = x >> 6, g = x & 63;
            sWrpT[g * 65 + f] = Wrp[x];
        }
        for (int x = tid; x < 128 * 64; x += 256) {
            int p = x >> 6, g = x & 63;
            sW1cT[g * 129 + p] = W1[p * 256 + 128 + g];
        }
        __syncthreads();
        const int d_base = blk * 64;
        const int grp = tid >> 6, t2 = tid & 63;
        for (int it = 0; it < 16; it++) {
            const int d = d_base + it * 4 + grp;
            if (t2 < 32 && d < 1023) {
                const float L2 = 11.005624549193878f;   // log2(2056)
                float x = (float)(d - 511) * exp2f(-(float)t2 * (L2 / 32.0f));
                float sv, cv;
                sincospif(x, &sv, &cv);
                semb[grp * 64 + t2] = sv;
                semb[grp * 64 + 32 + t2] = cv;
            }
            __syncthreads();
            if (d < 1023) {
                float acc = brp[t2];
                const float* em = semb + grp * 64;
                #pragma unroll
                for (int g = 0; g < 64; g++) acc = fmaf(em[g], sWrpT[g * 65 + t2], acc);
                srp[grp * 64 + t2] = acc;
            }
            __syncthreads();
            {
                const int p = tid & 127;
                #pragma unroll
                for (int dd = 0; dd < 2; dd++) {
                    const int dl = (tid >> 7) + 2 * dd;
                    const int dg = d_base + it * 4 + dl;
                    if (dg < 1023) {
                        float acc = 0.0f;
                        const float* rpp = srp + dl * 64;
                        #pragma unroll
                        for (int g = 0; g < 64; g++) acc = fmaf(rpp[g], sW1cT[g * 129 + p], acc);
                        g_C[dg * CP + p] = acc;
                    }
                }
            }
            __syncthreads();
        }
    } else if (blk == 16) {
        for (int x = tid; x < 64 * 128; x += 256) {
            int k = x >> 7, n = x & 127;
            unsigned short h, l;
            split2(W1[n * 256 + 192 + k], h, l);
            g_W1h[x] = h;
            g_W1l[x] = l;
        }
    } else {
        for (int x = tid; x < 128 * 128; x += 256) {
            int p = x >> 7, q = x & 127;
            unsigned short h, l;
            split2(W2[q * 128 + p], h, l);
            g_W2h[x] = h;
            g_W2l[x] = l;
        }
    }
}

// ======================= main persistent wmma kernel =======================
#define E_LD  72
#define W_LD  136
#define OFF_E    0                       // E hi/lo 2x(128x72 bf16)=36864; reused as 8x per-warp fp32 scratch 32x36
#define OFF_EL   18432
#define OFF_W1   36864                   // W1 hi 64x136 bf16 = 17408
#define OFF_W1L  54272
#define OFF_W2   71680                   // W2 hi 128x136 bf16 = 34816
#define OFF_W2L  106496
#define OFF_H    141312                  // H hi/lo 2x(128x136 bf16)
#define OFF_HL   176128
#define OFF_B2   210944                  // b2 fp32[128]
#define SMEM_TOTAL 211456

__global__ __launch_bounds__(256, 1)
void k_main(const float* __restrict__ t, const float* __restrict__ sct,
            const float* __restrict__ pre, const float* __restrict__ b2v,
            float* __restrict__ out) {
    extern __shared__ char smem[];
    __nv_bfloat16* sEh  = (__nv_bfloat16*)(smem + OFF_E);
    __nv_bfloat16* sEl  = (__nv_bfloat16*)(smem + OFF_EL);
    __nv_bfloat16* sW1h = (__nv_bfloat16*)(smem + OFF_W1);
    __nv_bfloat16* sW1l = (__nv_bfloat16*)(smem + OFF_W1L);
    __nv_bfloat16* sW2h = (__nv_bfloat16*)(smem + OFF_W2);
    __nv_bfloat16* sW2l = (__nv_bfloat16*)(smem + OFF_W2L);
    __nv_bfloat16* sHh  = (__nv_bfloat16*)(smem + OFF_H);
    __nv_bfloat16* sHl  = (__nv_bfloat16*)(smem + OFF_HL);
    float* sb2 = (float*)(smem + OFF_B2);
    float* stage = (float*)(smem + OFF_E);   // per-warp scratch overlays E

    const int tid = threadIdx.x;
    const int wid = tid >> 5;
    const int lane = tid & 31;
    const int wm = wid >> 1;      // warp M block: rows [wm*32, +32)
    const int wn = wid & 1;       // warp N block: cols [wn*64, +64)
    const int r8 = lane >> 2;     // epilogue: row-in-8
    const int c4 = lane & 3;      // epilogue: 8-col group
    float* wscr = stage + wid * (32 * 36);

    // ---- stage pre-split weights + b2 once ----
    {
        uint32_t* d1h = (uint32_t*)(smem + OFF_W1);
        uint32_t* d1l = (uint32_t*)(smem + OFF_W1L);
        const uint32_t* s1h = (const uint32_t*)g_W1h;
        const uint32_t* s1l = (const uint32_t*)g_W1l;
        for (int x = tid; x < 64 * 64; x += 256) {
            int k = x >> 6, c = x & 63;
            d1h[k * 68 + c] = s1h[x];
            d1l[k * 68 + c] = s1l[x];
        }
        uint32_t* d2h = (uint32_t*)(smem + OFF_W2);
        uint32_t* d2l = (uint32_t*)(smem + OFF_W2L);
        const uint32_t* s2h = (const uint32_t*)g_W2h;
        const uint32_t* s2l = (const uint32_t*)g_W2l;
        for (int x = tid; x < 128 * 64; x += 256) {
            int p = x >> 6, c = x & 63;
            d2h[p * 68 + c] = s2h[x];
            d2l[p * 68 + c] = s2l[x];
        }
        if (tid < 128) sb2[tid] = b2v[tid];
        __syncthreads();
    }

    for (int tile = blockIdx.x; tile < 2048; tile += gridDim.x) {
        const int i = tile >> 2;
        const int j0 = (tile & 3) << 7;

        // ---- build E: cols [rbf_t 0:22 | rbf_sc 22:44 | pre 44:64], split hi/lo ----
        {
            const int half = tid >> 7, m = tid & 127, j = j0 + m;
            const float* P = half ? sct : t;
            float dx = P[3 * i + 0] - P[3 * j + 0];
            float dy = P[3 * i + 1] - P[3 * j + 1];
            float dz = P[3 * i + 2] - P[3 * j + 2];
            float dist = sqrtf(dx * dx + dy * dy + dz * dz);
            const float inv_sig = 22.0f / 20.0f, step = 20.0f / 21.0f;
            uint32_t* Eh = (uint32_t*)(sEh + m * E_LD);
            uint32_t* El = (uint32_t*)(sEl + m * E_LD);
            float e[22];
            #pragma unroll
            for (int k = 0; k < 22; k++) {
                float r = (dist - k * step) * inv_sig;
                e[k] = __expf(-r * r);
            }
            const int ub = half * 11;
            #pragma unroll
            for (int c = 0; c < 11; c++) {
                unsigned short h0, l0, h1, l1;
                split2(e[2 * c], h0, l0);
                split2(e[2 * c + 1], h1, l1);
                Eh[ub + c] = (uint32_t)h0 | ((uint32_t)h1 << 16);
                El[ub + c] = (uint32_t)l0 | ((uint32_t)l1 << 16);
            }
            const float2* pp = (const float2*)(pre + ((size_t)(i * LSEQ + j)) * 20 + half * 10);
            #pragma unroll
            for (int c = 0; c < 5; c++) {
                float2 v = pp[c];
                unsigned short h0, l0, h1, l1;
                split2(v.x, h0, l0);
                split2(v.y, h1, l1);
                Eh[22 + half * 5 + c] = (uint32_t)h0 | ((uint32_t)h1 << 16);
                El[22 + half * 5 + c] = (uint32_t)l0 | ((uint32_t)l1 << 16);
            }
        }
        __syncthreads();

        wmma::fragment<wmma::accumulator, 16, 16, 16, float> acc[2][4];

        // ---- GEMM1: D1 = E @ W1s (K=64, 3 split passes) ----
        #pragma unroll
        for (int mi = 0; mi < 2; mi++)
            #pragma unroll
            for (int nb = 0; nb < 4; nb++) wmma::fill_fragment(acc[mi][nb], 0.0f);
        #pragma unroll 1
        for (int pass = 0; pass < 3; pass++) {
            const __nv_bfloat16* Ab = (pass == 1) ? sEl : sEh;
            const __nv_bfloat16* Bb = (pass == 2) ? sW1l : sW1h;
            #pragma unroll
            for (int ks = 0; ks < 4; ks++) {
                wmma::fragment<wmma::matrix_a, 16, 16, 16, __nv_bfloat16, wmma::row_major> a0, a1;
                wmma::load_matrix_sync(a0, Ab + (wm * 32) * E_LD + ks * 16, E_LD);
                wmma::load_matrix_sync(a1, Ab + (wm * 32 + 16) * E_LD + ks * 16, E_LD);
                #pragma unroll
                for (int nb = 0; nb < 4; nb++) {
                    wmma::fragment<wmma::matrix_b, 16, 16, 16, __nv_bfloat16, wmma::row_major> bf;
                    wmma::load_matrix_sync(bf, Bb + (ks * 16) * W_LD + wn * 64 + nb * 16, W_LD);
                    wmma::mma_sync(acc[0][nb], a0, bf, acc[0][nb]);
                    wmma::mma_sync(acc[1][nb], a1, bf, acc[1][nb]);
                }
            }
        }
        __syncthreads();   // E reads done; scratch may overwrite E region

        // ---- epilogue1 (warp-local): H = relu(D1 + A[i] + B[j] + C[i-j]) ----
        {
            const float* Ai = g_A + i * CP;
            #pragma unroll
            for (int h = 0; h < 2; h++) {
                wmma::store_matrix_sync(wscr,               acc[0][2 * h],     36, wmma::mem_row_major);
                wmma::store_matrix_sync(wscr + 16,          acc[0][2 * h + 1], 36, wmma::mem_row_major);
                wmma::store_matrix_sync(wscr + 16 * 36,     acc[1][2 * h],     36, wmma::mem_row_major);
                wmma::store_matrix_sync(wscr + 16 * 36 + 16,acc[1][2 * h + 1], 36, wmma::mem_row_major);
                __syncwarp();
                const int cb = wn * 64 + h * 32 + c4 * 8;
                const float4 a0 = ((const float4*)(Ai + cb))[0];
                const float4 a1 = ((const float4*)(Ai + cb))[1];
                #pragma unroll
                for (int rr = 0; rr < 4; rr++) {
                    const int rl = rr * 8 + r8;
                    const int m = wm * 32 + rl;
                    const int j = j0 + m;
                    const float* sp = wscr + rl * 36 + c4 * 8;
                    float4 s0 = ((const float4*)sp)[0], s1 = ((const float4*)sp)[1];
                    const float4* B4 = (const float4*)(g_B + j * CP + cb);
                    const float4* C4 = (const float4*)(g_C + (i - j + 511) * CP + cb);
                    float4 b0 = B4[0], b1 = B4[1], cc0 = C4[0], cc1 = C4[1];
                    float v0 = fmaxf(s0.x + a0.x + b0.x + cc0.x, 0.0f);
                    float v1 = fmaxf(s0.y + a0.y + b0.y + cc0.y, 0.0f);
                    float v2 = fmaxf(s0.z + a0.z + b0.z + cc0.z, 0.0f);
                    float v3 = fmaxf(s0.w + a0.w + b0.w + cc0.w, 0.0f);
                    float v4 = fmaxf(s1.x + a1.x + b1.x + cc1.x, 0.0f);
                    float v5 = fmaxf(s1.y + a1.y + b1.y + cc1.y, 0.0f);
                    float v6 = fmaxf(s1.z + a1.z + b1.z + cc1.z, 0.0f);
                    float v7 = fmaxf(s1.w + a1.w + b1.w + cc1.w, 0.0f);
                    uint32_t* Hh = (uint32_t*)(sHh + m * W_LD + cb);
                    uint32_t* Hl = (uint32_t*)(sHl + m * W_LD + cb);
                    unsigned short h0, l0, h1, l1;
                    split2(v0, h0, l0); split2(v1, h1, l1);
                    Hh[0] = (uint32_t)h0 | ((uint32_t)h1 << 16);
                    Hl[0] = (uint32_t)l0 | ((uint32_t)l1 << 16);
                    split2(v2, h0, l0); split2(v3, h1, l1);
                    Hh[1] = (uint32_t)h0 | ((uint32_t)h1 << 16);
                    Hl[1] = (uint32_t)l0 | ((uint32_t)l1 << 16);
                    split2(v4, h0, l0); split2(v5, h1, l1);
                    Hh[2] = (uint32_t)h0 | ((uint32_t)h1 << 16);
                    Hl[2] = (uint32_t)l0 | ((uint32_t)l1 << 16);
                    split2(v6, h0, l0); split2(v7, h1, l1);
                    Hh[3] = (uint32_t)h0 | ((uint32_t)h1 << 16);
                    Hl[3] = (uint32_t)l0 | ((uint32_t)l1 << 16);
                }
                __syncwarp();
            }
        }
        __syncthreads();   // all H written

        // ---- GEMM2: D2 = H @ W2t (K=128, 3 split passes) ----
        #pragma unroll
        for (int mi = 0; mi < 2; mi++)
            #pragma unroll
            for (int nb = 0; nb < 4; nb++) wmma::fill_fragment(acc[mi][nb], 0.0f);
        #pragma unroll 1
        for (int pass = 0; pass < 3; pass++) {
            const __nv_bfloat16* Ab = (pass == 1) ? sHl : sHh;
            const __nv_bfloat16* Bb = (pass == 2) ? sW2l : sW2h;
            #pragma unroll
            for (int ks = 0; ks < 8; ks++) {
                wmma::fragment<wmma::matrix_a, 16, 16, 16, __nv_bfloat16, wmma::row_major> a0, a1;
                wmma::load_matrix_sync(a0, Ab + (wm * 32) * W_LD + ks * 16, W_LD);
                wmma::load_matrix_sync(a1, Ab + (wm * 32 + 16) * W_LD + ks * 16, W_LD);
                #pragma unroll
                for (int nb = 0; nb < 4; nb++) {
                    wmma::fragment<wmma::matrix_b, 16, 16, 16, __nv_bfloat16, wmma::row_major> bf;
                    wmma::load_matrix_sync(bf, Bb + (ks * 16) * W_LD + wn * 64 + nb * 16, W_LD);
                    wmma::mma_sync(acc[0][nb], a0, bf, acc[0][nb]);
                    wmma::mma_sync(acc[1][nb], a1, bf, acc[1][nb]);
                }
            }
        }

        // ---- epilogue2 (warp-local): out = D2 + b2 ----
        {
            #pragma unroll
            for (int h = 0; h < 2; h++) {
                wmma::store_matrix_sync(wscr,               acc[0][2 * h],     36, wmma::mem_row_major);
                wmma::store_matrix_sync(wscr + 16,          acc[0][2 * h + 1], 36, wmma::mem_row_major);
                wmma::store_matrix_sync(wscr + 16 * 36,     acc[1][2 * h],     36, wmma::mem_row_major);
                wmma::store_matrix_sync(wscr + 16 * 36 + 16,acc[1][2 * h + 1], 36, wmma::mem_row_major);
                __syncwarp();
                const int cb = wn * 64 + h * 32 + c4 * 8;
                const float4 bb0 = ((const float4*)(sb2 + cb))[0];
                const float4 bb1 = ((const float4*)(sb2 + cb))[1];
                #pragma unroll
                for (int rr = 0; rr < 4; rr++) {
                    const int rl = rr * 8 + r8;
                    const int m = wm * 32 + rl;
                    const float* sp = wscr + rl * 36 + c4 * 8;
                    float4 s0 = ((const float4*)sp)[0], s1 = ((const float4*)sp)[1];
                    float4 r0, r1;
                    r0.x = s0.x + bb0.x; r0.y = s0.y + bb0.y;
                    r0.z = s0.z + bb0.z; r0.w = s0.w + bb0.w;
                    r1.x = s1.x + bb1.x; r1.y = s1.y + bb1.y;
                    r1.z = s1.z + bb1.z; r1.w = s1.w + bb1.w;
                    float4* O4 = (float4*)(out + ((size_t)(i * LSEQ + j0 + m)) * CP + cb);
                    O4[0] = r0;
                    O4[1] = r1;
                }
                __syncwarp();
            }
        }
        __syncthreads();   // scratch reads done before next tile's E build
    }
}

// ======================= launch =======================
extern "C" void kernel_launch(void* const* d_in, const int* in_sizes, int n_in,
                              void* d_out, int out_size) {
    const float* s   = (const float*)d_in[0];
    const float* t   = (const float*)d_in[1];
    const float* sct = (const float*)d_in[2];
    const float* pre = (const float*)d_in[3];
    // d_in[4] = p_mask (all-ones, unused)
    const float* Wsp = (const float*)d_in[5];
    const float* bsp = (const float*)d_in[6];
    const float* Wrp = (const float*)d_in[7];
    const float* brp = (const float*)d_in[8];
    const float* W1  = (const float*)d_in[9];
    const float* b1  = (const float*)d_in[10];
    const float* W2  = (const float*)d_in[11];
    const float* b2  = (const float*)d_in[12];
    float* out = (float*)d_out;

    const int p1_smem = (256 * 65 + 128 * 129 + 8 * 256 + 8 * 64) * 4;   // 142848
    const int p2_smem = (64 * 65 + 64 * 129 + 4 * 64 + 4 * 64) * 4;      // 51712
    cudaFuncSetAttribute(k_prep1, cudaFuncAttributeMaxDynamicSharedMemorySize, p1_smem);
    cudaFuncSetAttribute(k_prep2, cudaFuncAttributeMaxDynamicSharedMemorySize, p2_smem);
    k_prep1<<<64, 256, p1_smem>>>(s, Wsp, bsp, W1, b1);
    k_prep2<<<18, 256, p2_smem>>>(Wrp, brp, W1, W2);

    cudaFuncSetAttribute(k_main, cudaFuncAttributeMaxDynamicSharedMemorySize, SMEM_TOTAL);
    k_main<<<152, 256, SMEM_TOTAL>>>(t, sct, pre, b2, out);
}

// round 8
// speedup vs baseline: 1.8332x; 1.0022x over previous
#include <cuda_runtime.h>
#include <cuda_bf16.h>
#include <mma.h>
#include <cstdint>
#include <math.h>

using namespace nvcuda;

#define LSEQ 512
#define CP   128

// ======================= device globals (no allocation) =======================
__device__ float g_A[LSEQ * CP];            // b1 + p_i[i] . W1[:,0:64]
__device__ float g_B[LSEQ * CP];            // p_i[j] . W1[:,64:128]
__device__ float g_C[1023 * CP];            // relpos path . W1[:,128:192]

__device__ __forceinline__ float rtf32(float x) {
    float r;
    asm("cvt.rna.tf32.f32 %0, %1;" : "=f"(r) : "f"(x));
    return r;
}

// ======================= merged prep kernel =======================
// blocks 0..63 : A/B tables (8 i-rows each, weights staged transposed)
// blocks 64..79: C table (64 rel-pos values each)
__global__ void k_prep(const float* __restrict__ s, const float* __restrict__ Wsp,
                       const float* __restrict__ bsp, const float* __restrict__ Wrp,
                       const float* __restrict__ brp, const float* __restrict__ W1,
                       const float* __restrict__ b1) {
    extern __shared__ float sm1[];
    const int tid = threadIdx.x;   // 256
    const int blk = blockIdx.x;
    if (blk < 64) {
        float* sWspT = sm1;                        // [d=256][f=64] pad 65
        float* sW1T  = sm1 + 256 * 65;             // [c=128][p=128] pad 129
        float* srow  = sW1T + 128 * 129;           // [8][256]
        float* prow  = srow + 8 * 256;             // [8][64]
        const int ii0 = blk * 8;

        for (int x = tid; x < 64 * 256; x += 256) {
            int f = x >> 8, d = x & 255;
            sWspT[d * 65 + f] = Wsp[x];
        }
        for (int x = tid; x < 128 * 128; x += 256) {
            int p = x >> 7, c = x & 127;
            sW1T[c * 129 + p] = W1[p * 256 + c];
        }
        for (int x = tid; x < 8 * 256; x += 256)
            srow[x] = s[ii0 * 256 + x];
        __syncthreads();

        {
            const int f = tid & 63, il = tid >> 6;
            #pragma unroll
            for (int rep = 0; rep < 2; rep++) {
                const int i_loc = rep * 4 + il;
                float acc = bsp[f];
                const float* sr = srow + i_loc * 256;
                #pragma unroll 8
                for (int d = 0; d < 256; d++) acc = fmaf(sr[d], sWspT[d * 65 + f], acc);
                prow[i_loc * 64 + f] = acc;
            }
        }
        __syncthreads();
        {
            const int p = tid & 127, il = tid >> 7;
            #pragma unroll
            for (int rep = 0; rep < 4; rep++) {
                const int i_loc = rep * 2 + il;
                float a = b1[p], b = 0.0f;
                const float* pr = prow + i_loc * 64;
                #pragma unroll
                for (int fx = 0; fx < 64; fx++) {
                    float pv = pr[fx];
                    a = fmaf(pv, sW1T[fx * 129 + p], a);
                    b = fmaf(pv, sW1T[(64 + fx) * 129 + p], b);
                }
                g_A[(ii0 + i_loc) * CP + p] = a;
                g_B[(ii0 + i_loc) * CP + p] = b;
            }
        }
    } else {
        float* sWrpT  = sm1;                   // [g=64][f=64] pad 65
        float* sW1cT  = sm1 + 64 * 65;         // [g=64][p=128] pad 129
        float* semb   = sW1cT + 64 * 129;      // [4][64]
        float* srp    = semb + 4 * 64;         // [4][64]
        for (int x = tid; x < 64 * 64; x += 256) {
            int f = x >> 6, g = x & 63;
            sWrpT[g * 65 + f] = Wrp[x];
        }
        for (int x = tid; x < 128 * 64; x += 256) {
            int p = x >> 6, g = x & 63;
            sW1cT[g * 129 + p] = W1[p * 256 + 128 + g];
        }
        __syncthreads();
        const int d_base = (blk - 64) * 64;
        const int grp = tid >> 6, t2 = tid & 63;
        for (int it = 0; it < 16; it++) {
            const int d = d_base + it * 4 + grp;
            if (t2 < 32 && d < 1023) {
                const float L2 = 11.005624549193878f;   // log2(2056)
                float x = (float)(d - 511) * exp2f(-(float)t2 * (L2 / 32.0f));
                float sv, cv;
                sincospif(x, &sv, &cv);
                semb[grp * 64 + t2] = sv;
                semb[grp * 64 + 32 + t2] = cv;
            }
            __syncthreads();
            if (d < 1023) {
                float acc = brp[t2];
                const float* em = semb + grp * 64;
                #pragma unroll
                for (int g = 0; g < 64; g++) acc = fmaf(em[g], sWrpT[g * 65 + t2], acc);
                srp[grp * 64 + t2] = acc;
            }
            __syncthreads();
            {
                const int p = tid & 127;
                #pragma unroll
                for (int dd = 0; dd < 2; dd++) {
                    const int dl = (tid >> 7) + 2 * dd;
                    const int dg = d_base + it * 4 + dl;
                    if (dg < 1023) {
                        float acc = 0.0f;
                        const float* rpp = srp + dl * 64;
                        #pragma unroll
                        for (int g = 0; g < 64; g++) acc = fmaf(rpp[g], sW1cT[g * 129 + p], acc);
                        g_C[dg * CP + p] = acc;
                    }
                }
            }
            __syncthreads();
        }
    }
}

// ======================= main persistent tf32-wmma kernel =======================
#define E_LD  72
#define W_LD  132
#define OFF_W1   0                       // W1s^T [k=64][n=128+4] fp32 = 33792
#define OFF_W2   33792                   // W2^T  [p=128][q=128+4] fp32 = 67584
#define OFF_E    101376                  // E [128][72] fp32 = 36864 (reused: 8x warp scratch 32x36)
#define OFF_H    138240                  // H [128][132] fp32 = 67584
#define OFF_B2   205824                  // b2 fp32[128]
#define SMEM_TOTAL 206336

__global__ __launch_bounds__(256, 1)
void k_main(const float* __restrict__ t, const float* __restrict__ sct,
            const float* __restrict__ pre, const float* __restrict__ W1g,
            const float* __restrict__ W2g, const float* __restrict__ b2v,
            float* __restrict__ out) {
    extern __shared__ char smem[];
    float* sW1 = (float*)(smem + OFF_W1);
    float* sW2 = (float*)(smem + OFF_W2);
    float* sE  = (float*)(smem + OFF_E);
    float* sH  = (float*)(smem + OFF_H);
    float* sb2 = (float*)(smem + OFF_B2);
    float* stage = (float*)(smem + OFF_E);   // per-warp scratch overlays E

    const int tid = threadIdx.x;
    const int wid = tid >> 5;
    const int lane = tid & 31;
    const int wm = wid >> 1;      // warp M block: rows [wm*32, +32)
    const int wn = wid & 1;       // warp N block: cols [wn*64, +64)
    const int r8 = lane >> 2;     // epilogue: row-in-8
    const int c4 = lane & 3;      // epilogue: 8-col group
    float* wscr = stage + wid * (32 * 36);

    // ---- stage tf32-rounded transposed weights + b2 once (from raw gmem) ----
    {
        for (int x = tid; x < 128 * 64; x += 256) {
            int n = x >> 6, k = x & 63;                      // k fast -> coalesced read
            sW1[k * W_LD + n] = rtf32(W1g[n * 256 + 192 + k]);
        }
        for (int x = tid; x < 128 * 128; x += 256) {
            int q = x >> 7, p = x & 127;                     // p fast -> coalesced read
            sW2[p * W_LD + q] = rtf32(W2g[q * 128 + p]);
        }
        if (tid < 128) sb2[tid] = b2v[tid];
        __syncthreads();
    }

    for (int tile = blockIdx.x; tile < 2048; tile += gridDim.x) {
        const int i = tile >> 2;
        const int j0 = (tile & 3) << 7;

        // ---- build E: cols [rbf_t 0:22 | rbf_sc 22:44 | pre 44:64], tf32-rounded ----
        {
            const int half = tid >> 7, m = tid & 127, j = j0 + m;
            const float* P = half ? sct : t;
            float dx = P[3 * i + 0] - P[3 * j + 0];
            float dy = P[3 * i + 1] - P[3 * j + 1];
            float dz = P[3 * i + 2] - P[3 * j + 2];
            float dist = sqrtf(dx * dx + dy * dy + dz * dz);
            const float inv_sig = 22.0f / 20.0f, step = 20.0f / 21.0f;
            float* Er = sE + m * E_LD;
            #pragma unroll
            for (int k = 0; k < 22; k++) {
                float r = (dist - k * step) * inv_sig;
                Er[half * 22 + k] = rtf32(__expf(-r * r));
            }
            const float2* pp = (const float2*)(pre + ((size_t)(i * LSEQ + j)) * 20 + half * 10);
            #pragma unroll
            for (int c = 0; c < 5; c++) {
                float2 v = pp[c];
                Er[44 + half * 10 + 2 * c]     = rtf32(v.x);
                Er[44 + half * 10 + 2 * c + 1] = rtf32(v.y);
            }
        }
        __syncthreads();

        wmma::fragment<wmma::accumulator, 16, 16, 8, float> acc[2][4];

        // ---- GEMM1: D1 = E @ W1s (K=64, tf32 single pass) ----
        #pragma unroll
        for (int mi = 0; mi < 2; mi++)
            #pragma unroll
            for (int nb = 0; nb < 4; nb++) wmma::fill_fragment(acc[mi][nb], 0.0f);
        #pragma unroll
        for (int ks = 0; ks < 8; ks++) {
            wmma::fragment<wmma::matrix_a, 16, 16, 8, wmma::precision::tf32, wmma::row_major> a0, a1;
            wmma::load_matrix_sync(a0, sE + (wm * 32) * E_LD + ks * 8, E_LD);
            wmma::load_matrix_sync(a1, sE + (wm * 32 + 16) * E_LD + ks * 8, E_LD);
            #pragma unroll
            for (int nb = 0; nb < 4; nb++) {
                wmma::fragment<wmma::matrix_b, 16, 16, 8, wmma::precision::tf32, wmma::row_major> bf;
                wmma::load_matrix_sync(bf, sW1 + (ks * 8) * W_LD + wn * 64 + nb * 16, W_LD);
                wmma::mma_sync(acc[0][nb], a0, bf, acc[0][nb]);
                wmma::mma_sync(acc[1][nb], a1, bf, acc[1][nb]);
            }
        }
        __syncthreads();   // E reads done; scratch may overwrite E region

        // ---- epilogue1 (warp-local): H = tf32(relu(D1 + A[i] + B[j] + C[i-j])) ----
        {
            const float* Ai = g_A + i * CP;
            #pragma unroll
            for (int h = 0; h < 2; h++) {
                wmma::store_matrix_sync(wscr,                acc[0][2 * h],     36, wmma::mem_row_major);
                wmma::store_matrix_sync(wscr + 16,           acc[0][2 * h + 1], 36, wmma::mem_row_major);
                wmma::store_matrix_sync(wscr + 16 * 36,      acc[1][2 * h],     36, wmma::mem_row_major);
                wmma::store_matrix_sync(wscr + 16 * 36 + 16, acc[1][2 * h + 1], 36, wmma::mem_row_major);
                __syncwarp();
                const int cb = wn * 64 + h * 32 + c4 * 8;
                const float4 a0 = ((const float4*)(Ai + cb))[0];
                const float4 a1 = ((const float4*)(Ai + cb))[1];
                #pragma unroll
                for (int rr = 0; rr < 4; rr++) {
                    const int rl = rr * 8 + r8;
                    const int m = wm * 32 + rl;
                    const int j = j0 + m;
                    const float* sp = wscr + rl * 36 + c4 * 8;
                    float4 s0 = ((const float4*)sp)[0], s1 = ((const float4*)sp)[1];
                    const float4* B4 = (const float4*)(g_B + j * CP + cb);
                    const float4* C4 = (const float4*)(g_C + (i - j + 511) * CP + cb);
                    float4 b0 = B4[0], b1 = B4[1], cc0 = C4[0], cc1 = C4[1];
                    float4 h0, h1;
                    h0.x = rtf32(fmaxf(s0.x + a0.x + b0.x + cc0.x, 0.0f));
                    h0.y = rtf32(fmaxf(s0.y + a0.y + b0.y + cc0.y, 0.0f));
                    h0.z = rtf32(fmaxf(s0.z + a0.z + b0.z + cc0.z, 0.0f));
                    h0.w = rtf32(fmaxf(s0.w + a0.w + b0.w + cc0.w, 0.0f));
                    h1.x = rtf32(fmaxf(s1.x + a1.x + b1.x + cc1.x, 0.0f));
                    h1.y = rtf32(fmaxf(s1.y + a1.y + b1.y + cc1.y, 0.0f));
                    h1.z = rtf32(fmaxf(s1.z + a1.z + b1.z + cc1.z, 0.0f));
                    h1.w = rtf32(fmaxf(s1.w + a1.w + b1.w + cc1.w, 0.0f));
                    float4* Hw = (float4*)(sH + m * W_LD + cb);
                    Hw[0] = h0;
                    Hw[1] = h1;
                }
                __syncwarp();
            }
        }
        __syncthreads();   // all H written

        // ---- GEMM2: D2 = H @ W2t (K=128, tf32 single pass) ----
        #pragma unroll
        for (int mi = 0; mi < 2; mi++)
            #pragma unroll
            for (int nb = 0; nb < 4; nb++) wmma::fill_fragment(acc[mi][nb], 0.0f);
        #pragma unroll
        for (int ks = 0; ks < 16; ks++) {
            wmma::fragment<wmma::matrix_a, 16, 16, 8, wmma::precision::tf32, wmma::row_major> a0, a1;
            wmma::load_matrix_sync(a0, sH + (wm * 32) * W_LD + ks * 8, W_LD);
            wmma::load_matrix_sync(a1, sH + (wm * 32 + 16) * W_LD + ks * 8, W_LD);
            #pragma unroll
            for (int nb = 0; nb < 4; nb++) {
                wmma::fragment<wmma::matrix_b, 16, 16, 8, wmma::precision::tf32, wmma::row_major> bf;
                wmma::load_matrix_sync(bf, sW2 + (ks * 8) * W_LD + wn * 64 + nb * 16, W_LD);
                wmma::mma_sync(acc[0][nb], a0, bf, acc[0][nb]);
                wmma::mma_sync(acc[1][nb], a1, bf, acc[1][nb]);
            }
        }

        // ---- epilogue2 (warp-local): out = D2 + b2 ----
        {
            #pragma unroll
            for (int h = 0; h < 2; h++) {
                wmma::store_matrix_sync(wscr,                acc[0][2 * h],     36, wmma::mem_row_major);
                wmma::store_matrix_sync(wscr + 16,           acc[0][2 * h + 1], 36, wmma::mem_row_major);
                wmma::store_matrix_sync(wscr + 16 * 36,      acc[1][2 * h],     36, wmma::mem_row_major);
                wmma::store_matrix_sync(wscr + 16 * 36 + 16, acc[1][2 * h + 1], 36, wmma::mem_row_major);
                __syncwarp();
                const int cb = wn * 64 + h * 32 + c4 * 8;
                const float4 bb0 = ((const float4*)(sb2 + cb))[0];
                const float4 bb1 = ((const float4*)(sb2 + cb))[1];
                #pragma unroll
                for (int rr = 0; rr < 4; rr++) {
                    const int rl = rr * 8 + r8;
                    const int m = wm * 32 + rl;
                    const float* sp = wscr + rl * 36 + c4 * 8;
                    float4 s0 = ((const float4*)sp)[0], s1 = ((const float4*)sp)[1];
                    float4 r0, r1;
                    r0.x = s0.x + bb0.x; r0.y = s0.y + bb0.y;
                    r0.z = s0.z + bb0.z; r0.w = s0.w + bb0.w;
                    r1.x = s1.x + bb1.x; r1.y = s1.y + bb1.y;
                    r1.z = s1.z + bb1.z; r1.w = s1.w + bb1.w;
                    float4* O4 = (float4*)(out + ((size_t)(i * LSEQ + j0 + m)) * CP + cb);
                    O4[0] = r0;
                    O4[1] = r1;
                }
                __syncwarp();
            }
        }
        __syncthreads();   // scratch reads done before next tile's E build
    }
}

// ======================= launch =======================
extern "C" void kernel_launch(void* const* d_in, const int* in_sizes, int n_in,
                              void* d_out, int out_size) {
    const float* s   = (const float*)d_in[0];
    const float* t   = (const float*)d_in[1];
    const float* sct = (const float*)d_in[2];
    const float* pre = (const float*)d_in[3];
    // d_in[4] = p_mask (all-ones, unused)
    const float* Wsp = (const float*)d_in[5];
    const float* bsp = (const float*)d_in[6];
    const float* Wrp = (const float*)d_in[7];
    const float* brp = (const float*)d_in[8];
    const float* W1  = (const float*)d_in[9];
    const float* b1  = (const float*)d_in[10];
    const float* W2  = (const float*)d_in[11];
    const float* b2  = (const float*)d_in[12];
    float* out = (float*)d_out;

    const int p_smem = (256 * 65 + 128 * 129 + 8 * 256 + 8 * 64) * 4;   // 142848
    cudaFuncSetAttribute(k_prep, cudaFuncAttributeMaxDynamicSharedMemorySize, p_smem);
    k_prep<<<80, 256, p_smem>>>(s, Wsp, bsp, Wrp, brp, W1, b1);

    cudaFuncSetAttribute(k_main, cudaFuncAttributeMaxDynamicSharedMemorySize, SMEM_TOTAL);
    k_main<<<152, 256, SMEM_TOTAL>>>(t, sct, pre, W1, W2, b2, out);
}